// round 17
// baseline (speedup 1.0000x reference)
#include <cuda_runtime.h>
#include <cuda_bf16.h>
#include <cstdint>

// 2-layer LSTM, B=4096, H=300, T=64 — ONE persistent kernel over all 128
// cell-steps. tcgen05 bf16-split MMA (hi*hi+hi*lo+lo*hi), D in TMEM fp32.
// Per CTA: M=128 x N=304 (300+4 pad), grid 32x4=128 co-resident CTAs with a
// device-wide barrier between cells. Recurrent phase first: stage 0 of the
// next cell prefetched across the barrier (overlaps epilogue); stage 1
// prefetched after copy-out (overlaps the barrier). Epilogue on all 8 warps
// with PAIRED LDTMs (two 32-col loads per wait). SW128 bases 1024-aligned.

#if defined(__CUDA_ARCH_FEAT_SM103_ALL) || defined(__CUDA_ARCH_FEAT_SM100_ALL) || \
    defined(__CUDA_ARCH_FEAT_SM101_ALL) ||                                        \
    (defined(__CUDA_ARCH_FAMILY_SPECIFIC__) && (__CUDA_ARCH_FAMILY_SPECIFIC__ >= 1000))
#define LSTM_TC 1
#else
#define LSTM_TC 0
#endif

#define SW128(o) ((o) ^ (((o) >> 3) & 0x70))

namespace {
constexpr int Bx = 4096, Hd = 300, Tn = 64;
constexpr int Kp = 320;
constexpr int BM = 128, BNp = 304, BK = 64;
constexpr int NHs = 75;               // real h-groups per CTA
constexpr int NKT = 5;
constexpr int NIT = 10;
constexpr int NMT = Bx / BM;          // 32
constexpr int NNT = 4;
constexpr int CELLS = 2 * Tn;         // 128
constexpr int A_TILE = BM * 128;      // 16384
constexpr int B_TILE = BNp * 128;     // 38912
constexpr int WMAT = NNT * NKT * BNp * BK;
constexpr unsigned IDESC = (1u << 4) | (1u << 7) | (1u << 10) |
                           ((152 / 8) << 17) | ((BM / 16) << 24);  // N=152/MMA
constexpr unsigned long long DESC_BASE =
    (2ull << 61) | (1ull << 46) | (64ull << 32) | (1ull << 16);
// smem head
constexpr int SM_TMEM = 0;
constexpr int SM_FULL = 8;            // 2 mbarriers: 8,16
constexpr int SM_DONE = 24;           // 2 mbarriers: 24,32
constexpr int SM_BIAS = 64;           // 2 x 304 floats
constexpr int ST_A_HI = 0;
constexpr int ST_A_LO = A_TILE;
constexpr int ST_B_HI = 2 * A_TILE;
constexpr int ST_B_LO = 2 * A_TILE + B_TILE;
constexpr int STAGE_SZ = 2 * A_TILE + 2 * B_TILE;   // 110592
constexpr int SM_STAGE0 = 4096;
constexpr int SM_TOTAL = SM_STAGE0 + 2 * STAGE_SZ;  // 225280
// epilogue staging overlays STAGE 1 (free after final DONE; re-filled only
// after copy-out consumes it)
constexpr int EP_HHI = SM_STAGE0 + STAGE_SZ;
constexpr int EP_HLO = EP_HHI + BM * NHs * 2;
constexpr int EP_Y   = EP_HLO + BM * NHs * 2;
}

// ---- persistent device state -------------------------------------------
__device__ __align__(1024) __nv_bfloat16 g_WHi[4][WMAT];  // ih0,hh0,ih1,hh1
__device__ __align__(1024) __nv_bfloat16 g_WLo[4][WMAT];
__device__ __align__(1024) __nv_bfloat16 g_actHi[5][Bx * Kp];
__device__ __align__(1024) __nv_bfloat16 g_actLo[5][Bx * Kp];
__device__ float g_bias[2][4 * Hd];
__device__ float g_c[2][Hd * Bx];
__device__ unsigned g_bar;

__device__ __forceinline__ float sigmoid_f(float v) {
  return __fdividef(1.0f, 1.0f + __expf(-v));
}
__device__ __forceinline__ float tanh_f(float v) {
  return 2.0f * __fdividef(1.0f, 1.0f + __expf(-2.0f * v)) - 1.0f;
}

__device__ __forceinline__ void grid_barrier(int epoch, int tid) {
  __threadfence();
  __syncthreads();
  if (tid == 0) {
    atomicAdd(&g_bar, 1u);
    const unsigned target = 128u * (unsigned)epoch;
    unsigned v = 0, spins = 0;
    do {
      asm volatile("ld.acquire.gpu.u32 %0, [%1];" : "=r"(v) : "l"(&g_bar)
                   : "memory");
    } while (v < target && ++spins < (1u << 22));
  }
  __syncthreads();
}

#if LSTM_TC
__device__ __forceinline__ void mma_f16_ss(uint32_t d, unsigned long long da,
                                           unsigned long long db, uint32_t en) {
  asm volatile(
      "{\n\t.reg .pred p;\n\tsetp.ne.u32 p, %4, 0;\n\t"
      "tcgen05.mma.cta_group::1.kind::f16 [%0], %1, %2, %3, {%5, %5, %5, %5}, p;\n\t}"
      :: "r"(d), "l"(da), "l"(db), "r"(IDESC), "r"(en), "r"(0u) : "memory");
}
__device__ __forceinline__ void mbar_wait(uint32_t mbar, uint32_t parity) {
  uint32_t done;
  asm volatile(
      "{\n\t.reg .pred p;\n\t"
      "mbarrier.try_wait.parity.acquire.cta.shared::cta.b64 p, [%1], %2;\n\t"
      "selp.b32 %0, 1, 0, p;\n\t}"
      : "=r"(done) : "r"(mbar), "r"(parity) : "memory");
  if (!done) {
    asm volatile(
        "{\n\t.reg .pred P1;\n\t"
        "W_%=:\n\t"
        "mbarrier.try_wait.parity.acquire.cta.shared::cta.b64 P1, [%0], %1, 0x989680;\n\t"
        "@P1 bra.uni D_%=;\n\t"
        "bra.uni W_%=;\n\t"
        "D_%=:\n\t}"
        :: "r"(mbar), "r"(parity) : "memory");
  }
}
__device__ __forceinline__ void bulk_cp(uint32_t dst, const void* src,
                                        uint32_t bytes, uint32_t mbar) {
  asm volatile(
      "cp.async.bulk.shared::cta.global.mbarrier::complete_tx::bytes "
      "[%0], [%1], %2, [%3];"
      :: "r"(dst), "l"(src), "r"(bytes), "r"(mbar) : "memory");
}
__device__ __forceinline__ void expect_tx(uint32_t mbar, uint32_t bytes) {
  asm volatile("mbarrier.arrive.expect_tx.shared.b64 _, [%0], %1;"
               :: "r"(mbar), "r"(bytes) : "memory");
}
__device__ __forceinline__ void ldtm_x32(uint32_t* r, uint32_t a) {
  asm volatile(
      "tcgen05.ld.sync.aligned.32x32b.x32.b32 "
      "{%0,%1,%2,%3,%4,%5,%6,%7,%8,%9,%10,%11,%12,%13,%14,%15,"
      "%16,%17,%18,%19,%20,%21,%22,%23,%24,%25,%26,%27,%28,%29,%30,%31}, [%32];"
      : "=r"(r[0]), "=r"(r[1]), "=r"(r[2]), "=r"(r[3]), "=r"(r[4]), "=r"(r[5]),
        "=r"(r[6]), "=r"(r[7]), "=r"(r[8]), "=r"(r[9]), "=r"(r[10]), "=r"(r[11]),
        "=r"(r[12]), "=r"(r[13]), "=r"(r[14]), "=r"(r[15]), "=r"(r[16]),
        "=r"(r[17]), "=r"(r[18]), "=r"(r[19]), "=r"(r[20]), "=r"(r[21]),
        "=r"(r[22]), "=r"(r[23]), "=r"(r[24]), "=r"(r[25]), "=r"(r[26]),
        "=r"(r[27]), "=r"(r[28]), "=r"(r[29]), "=r"(r[30]), "=r"(r[31])
      : "r"(a));
}
__device__ __forceinline__ void ldtm_x16(uint32_t* r, uint32_t a) {
  asm volatile(
      "tcgen05.ld.sync.aligned.32x32b.x16.b32 "
      "{%0,%1,%2,%3,%4,%5,%6,%7,%8,%9,%10,%11,%12,%13,%14,%15}, [%16];"
      : "=r"(r[0]), "=r"(r[1]), "=r"(r[2]), "=r"(r[3]), "=r"(r[4]), "=r"(r[5]),
        "=r"(r[6]), "=r"(r[7]), "=r"(r[8]), "=r"(r[9]), "=r"(r[10]), "=r"(r[11]),
        "=r"(r[12]), "=r"(r[13]), "=r"(r[14]), "=r"(r[15])
      : "r"(a));
}
#endif  // LSTM_TC

__device__ __forceinline__ void cell_bufs(int cell, int& xb, int& rb, int& hob) {
  int L = cell & 1, t = cell >> 1, cur = t & 1, nxt = cur ^ 1;
  if (L == 0) {
    xb = (t == 0) ? 0 : (3 + cur);
    rb = 1 + cur;
    hob = 1 + nxt;
  } else {
    xb = 1 + nxt;
    rb = 3 + cur;
    hob = 3 + nxt;
  }
}

// ---- prep ---------------------------------------------------------------
__global__ void prep_kernel(const float* __restrict__ z,
                            const float* __restrict__ Wih0,
                            const float* __restrict__ Whh0,
                            const float* __restrict__ bih0,
                            const float* __restrict__ bhh0,
                            const float* __restrict__ Wih1,
                            const float* __restrict__ Whh1,
                            const float* __restrict__ bih1,
                            const float* __restrict__ bhh1) {
  const int stride = gridDim.x * blockDim.x;
  const int g0 = blockIdx.x * blockDim.x + threadIdx.x;
  if (g0 == 0) g_bar = 0u;
  const float* Ws[4] = {Wih0, Whh0, Wih1, Whh1};
  char* wHiB = (char*)g_WHi;
  char* wLoB = (char*)g_WLo;
  for (int idx = g0; idx < 4 * WMAT; idx += stride) {
    int mi = idx / WMAT;
    int rem = idx - mi * WMAT;
    int tile = rem / (BNp * BK);
    int e = rem - tile * (BNp * BK);
    int r = e / BK, cc = e - (e / BK) * BK;
    int ntt = tile / NKT, ktt = tile - ntt * NKT;
    int k = ktt * BK + cc;
    float w = 0.f;
    if (r < 300 && k < Hd) {
      int n = ntt * 300 + r;
      int h = n >> 2, gg = n & 3;
      w = Ws[mi][(gg * Hd + h) * Hd + k];
    }
    __nv_bfloat16 hi = __float2bfloat16(w);
    size_t off = (size_t)mi * ((size_t)WMAT * 2) + (size_t)tile * B_TILE +
                 SW128(r * 128 + cc * 2);
    *(__nv_bfloat16*)(wHiB + off) = hi;
    *(__nv_bfloat16*)(wLoB + off) = __float2bfloat16(w - __bfloat162float(hi));
  }
  for (int idx = g0; idx < 2 * 4 * Hd; idx += stride) {
    int n = idx % (4 * Hd), cell = idx / (4 * Hd);
    int h = n >> 2, gg = n & 3;
    g_bias[cell][n] = cell ? (bih1[gg * Hd + h] + bhh1[gg * Hd + h])
                           : (bih0[gg * Hd + h] + bhh0[gg * Hd + h]);
  }
  char* aHiB = (char*)g_actHi;
  char* aLoB = (char*)g_actLo;
  for (int idx = g0; idx < Bx * Kp; idx += stride) {
    int k = idx % Kp, m = idx / Kp;
    float v = (k < Hd) ? z[m * Hd + k] : 0.f;
    __nv_bfloat16 hi = __float2bfloat16(v);
    int mt = m / BM, r = m % BM, kt = k / BK, cc = k % BK;
    size_t off = (size_t)(mt * NKT + kt) * A_TILE + SW128(r * 128 + cc * 2);
    *(__nv_bfloat16*)(aHiB + off) = hi;
    *(__nv_bfloat16*)(aLoB + off) = __float2bfloat16(v - __bfloat162float(hi));
  }
  uint4* zh = (uint4*)(g_actHi[1]);
  uint4* zl = (uint4*)(g_actLo[1]);
  const int nq = 4 * Bx * Kp * 2 / 16;
  uint4 zz = {0u, 0u, 0u, 0u};
  for (int idx = g0; idx < nq; idx += stride) { zh[idx] = zz; zl[idx] = zz; }
  for (int idx = g0; idx < Hd * Bx; idx += stride) {
    g_c[0][idx] = 0.f;
    g_c[1][idx] = 0.f;
  }
}

// ---- persistent fused kernel --------------------------------------------
__global__ __launch_bounds__(256) void lstm_persist_kernel(float* __restrict__ Y) {
  extern __shared__ __align__(1024) char smem[];
  const uint32_t sbase = (uint32_t)__cvta_generic_to_shared(smem);
  const int tid = threadIdx.x;
  const int wid = tid >> 5, lid = tid & 31;
  const int mt = blockIdx.x;
  const int nt = blockIdx.y;
  const int m0 = mt * BM;

#if LSTM_TC
  if (wid == 0) {
    asm volatile(
        "tcgen05.alloc.cta_group::1.sync.aligned.shared::cta.b32 [%0], %1;"
        :: "r"(sbase + SM_TMEM), "r"(512u) : "memory");
  }
  if (tid == 0) {
    #pragma unroll
    for (int s = 0; s < 2; ++s) {
      asm volatile("mbarrier.init.shared.b64 [%0], 1;"
                   :: "r"(sbase + SM_FULL + 8 * s) : "memory");
      asm volatile("mbarrier.init.shared.b64 [%0], 1;"
                   :: "r"(sbase + SM_DONE + 8 * s) : "memory");
    }
  }
#endif
  for (int i = tid; i < 2 * BNp; i += 256) {
    int L = i / BNp, col = i - L * BNp;
    float b = (col < 300) ? g_bias[L][nt * 300 + col] : 0.f;
    ((float*)(smem + SM_BIAS))[L * BNp + col] = b;
  }
  __syncthreads();

#if LSTM_TC
  uint32_t tmem_base;
  asm volatile("ld.shared.b32 %0, [%1];"
               : "=r"(tmem_base) : "r"(sbase + SM_TMEM));
  const uint32_t dD = tmem_base;
  const bool l0 = (lid == 0);

  // combined A+B issue. j<NKT = recurrent (Whh, h two cells old); j>=NKT =
  // input phase (Wih, h from previous cell).
  auto issueAB = [&](int G) {
    if (!l0) return;
    int c = G / NIT, j = G - (G / NIT) * NIT;
    int phr = (j < NKT);
    int kt = phr ? j : (j - NKT);
    int s = j & 1;
    int xb, rb, hob;
    cell_bufs(c, xb, rb, hob);
    int ab = phr ? rb : xb;
    int mi = 2 * (c & 1) + (phr ? 1 : 0);
    const char* ah = (const char*)g_actHi[ab];
    const char* al = (const char*)g_actLo[ab];
    const char* bh = (const char*)g_WHi[mi];
    const char* bl = (const char*)g_WLo[mi];
    uint32_t stb = sbase + SM_STAGE0 + s * STAGE_SZ;
    uint32_t mb = sbase + SM_FULL + 8 * s;
    expect_tx(mb, (uint32_t)STAGE_SZ);
    size_t aoff = (size_t)(mt * NKT + kt) * A_TILE;
    size_t boff = (size_t)(nt * NKT + kt) * B_TILE;
    bulk_cp(stb + ST_A_HI, ah + aoff, A_TILE, mb);
    bulk_cp(stb + ST_A_LO, al + aoff, A_TILE, mb);
    bulk_cp(stb + ST_B_HI, bh + boff, B_TILE, mb);
    bulk_cp(stb + ST_B_LO, bl + boff, B_TILE, mb);
  };

  __nv_bfloat16* hst_hi = (__nv_bfloat16*)(smem + EP_HHI);
  __nv_bfloat16* hst_lo = (__nv_bfloat16*)(smem + EP_HLO);
  float* yst = (float*)(smem + EP_Y);

  #pragma unroll 1
  for (int cell = 0; cell < CELLS; ++cell) {
    const int G0 = cell * NIT;
    const int L = cell & 1, t = cell >> 1;
    int xb, rb, hob;
    cell_bufs(cell, xb, rb, hob);
    float* C = g_c[L];
    const float* bsm = (const float*)(smem + SM_BIAS) + L * BNp;

    if (wid == 0) {
      if (cell == 0) {
        issueAB(0);
        issueAB(1);
      } else {
        // stages 0 AND 1 already prefetched across the barrier (recurrent
        // phase depends only on h from two cells ago). Fence for X-phase
        // loads issued in-loop below.
        asm volatile("fence.proxy.async;" ::: "memory");
      }
      #pragma unroll 1
      for (int j = 0; j < NIT; ++j) {
        const int G = G0 + j;
        const int s = j & 1;
        const uint32_t par = (uint32_t)((G >> 1) & 1);
        mbar_wait(sbase + SM_FULL + 8 * s, par);
        if (l0) {
          const uint32_t stb = sbase + SM_STAGE0 + s * STAGE_SZ;
          unsigned long long dAh = DESC_BASE | (((stb + ST_A_HI) >> 4) & 0x3FFF);
          unsigned long long dAl = DESC_BASE | (((stb + ST_A_LO) >> 4) & 0x3FFF);
          unsigned long long dBh = DESC_BASE | (((stb + ST_B_HI) >> 4) & 0x3FFF);
          unsigned long long dBl = DESC_BASE | (((stb + ST_B_LO) >> 4) & 0x3FFF);
          #pragma unroll
          for (int k16 = 0; k16 < 4; ++k16) {
            unsigned long long off = k16 * 2;
            uint32_t en0 = !(j == 0 && k16 == 0);
            #pragma unroll
            for (int half = 0; half < 2; ++half) {
              unsigned long long bo = off + half * 1216;  // +152 rows
              uint32_t dDh = dD + half * 152;
              mma_f16_ss(dDh, dAh + off, dBh + bo, en0);
              mma_f16_ss(dDh, dAh + off, dBl + bo, 1);
              mma_f16_ss(dDh, dAl + off, dBh + bo, 1);
            }
          }
          asm volatile(
              "tcgen05.commit.cta_group::1.mbarrier::arrive::one.shared::cluster.b64 [%0];"
              :: "r"(sbase + SM_DONE + 8 * s) : "memory");
        }
        if (j <= NIT - 3) {
          mbar_wait(sbase + SM_DONE + 8 * s, par);
          issueAB(G + 2);
        }
      }
      // drain stage0 (j=8) -> prefetch next cell stage0 (overlaps epilogue);
      // then drain stage1 (j=9). Stage1 prefetch happens after copy-out.
      mbar_wait(sbase + SM_DONE + 0, (uint32_t)(((G0 + 8) >> 1) & 1));
      if (cell < CELLS - 1) issueAB(G0 + NIT);
      mbar_wait(sbase + SM_DONE + 8, (uint32_t)(((G0 + 9) >> 1) & 1));
    }
    __syncthreads();

    // ---- fused LSTM epilogue: 8 warps, paired LDTM ----------------------
    {
      asm volatile("tcgen05.fence::after_thread_sync;" ::: "memory");
      const int grp = wid >> 2;            // 0: cbi 0-4, 1: cbi 5-9
      const int ml = (wid & 3) * 32 + lid;
      const int m = m0 + ml;
      const int hg0 = nt * NHs;
      uint32_t r0[32], r1[32];

      auto proc = [&](const uint32_t* r, int cbi, int nh) {
        const int cb = cbi * 32;
        #pragma unroll
        for (int j2 = 0; j2 < 8; ++j2) {
          if (j2 >= nh) break;
          const int col = cb + j2 * 4;
          const int hgl = col >> 2;
          float vi = __uint_as_float(r[j2 * 4 + 0]) + bsm[col + 0];
          float vf = __uint_as_float(r[j2 * 4 + 1]) + bsm[col + 1];
          float vg = __uint_as_float(r[j2 * 4 + 2]) + bsm[col + 2];
          float vo = __uint_as_float(r[j2 * 4 + 3]) + bsm[col + 3];
          float i_ = sigmoid_f(vi);
          float f_ = sigmoid_f(vf);
          float g_ = tanh_f(vg);
          float o_ = sigmoid_f(vo);
          size_t ci = (size_t)(hg0 + hgl) * Bx + m;
          float c = f_ * C[ci] + i_ * g_;
          float h = o_ * tanh_f(c);
          C[ci] = c;
          __nv_bfloat16 hi = __float2bfloat16(h);
          hst_hi[ml * NHs + hgl] = hi;
          hst_lo[ml * NHs + hgl] = __float2bfloat16(h - __bfloat162float(hi));
          if (L) yst[ml * NHs + hgl] = h;
        }
      };

      #pragma unroll 1
      for (int pp = 0; pp < 3; ++pp) {
        const int cbi0 = grp * 5 + pp * 2;
        if (pp < 2) {
          ldtm_x32(r0, dD + cbi0 * 32);
          ldtm_x32(r1, dD + cbi0 * 32 + 32);
          asm volatile("tcgen05.wait::ld.sync.aligned;" ::: "memory");
          proc(r0, cbi0, 8);
          proc(r1, cbi0 + 1, 8);
        } else if (grp == 0) {
          ldtm_x32(r0, dD + cbi0 * 32);
          asm volatile("tcgen05.wait::ld.sync.aligned;" ::: "memory");
          proc(r0, cbi0, 8);
        } else {
          ldtm_x16(r0, dD + cbi0 * 32);
          asm volatile("tcgen05.wait::ld.sync.aligned;" ::: "memory");
          proc(r0, cbi0, 3);
        }
      }
    }
    __syncthreads();
    // ---- copy-out --------------------------------------------------------
    {
      char* hoHiB = (char*)g_actHi[hob];
      char* hoLoB = (char*)g_actLo[hob];
      for (int e = tid; e < BM * NHs; e += 256) {
        int m2 = e / NHs, j3 = e - (e / NHs) * NHs;
        int hg = nt * NHs + j3;
        int kt2 = hg >> 6, cc = hg & 63;
        size_t off = (size_t)(mt * NKT + kt2) * A_TILE + SW128(m2 * 128 + cc * 2);
        *(__nv_bfloat16*)(hoHiB + off) = hst_hi[e];
        *(__nv_bfloat16*)(hoLoB + off) = hst_lo[e];
      }
      if (L) {
        for (int e = tid; e < BM * NHs; e += 256) {
          int m2 = e / NHs, j3 = e - (e / NHs) * NHs;
          int hg = nt * NHs + j3;
          Y[(size_t)(m0 + m2) * (Tn * Hd) + (size_t)t * Hd + hg] = yst[e];
        }
      }
    }
    if (cell < CELLS - 1) {
      // staging fully consumed -> safe to refill stage 1 (overlaps barrier)
      __syncthreads();
      if (wid == 0) issueAB(G0 + NIT + 1);
      grid_barrier(cell + 1, tid);
    }
  }

  __syncthreads();
  if (tid == 0) {
    #pragma unroll
    for (int s = 0; s < 2; ++s) {
      asm volatile("mbarrier.inval.shared.b64 [%0];"
                   :: "r"(sbase + SM_FULL + 8 * s) : "memory");
      asm volatile("mbarrier.inval.shared.b64 [%0];"
                   :: "r"(sbase + SM_DONE + 8 * s) : "memory");
    }
  }
  if (wid == 0) {
    asm volatile("tcgen05.relinquish_alloc_permit.cta_group::1.sync.aligned;");
    asm volatile("tcgen05.dealloc.cta_group::1.sync.aligned.b32 %0, %1;"
                 :: "r"(tmem_base), "r"(512u));
  }
#else
  // ---- SIMT fallback ----------------------------------------------------
  const int f_row = tid >> 1;
  const int f_ch = tid & 1;
  #pragma unroll 1
  for (int cell = 0; cell < CELLS; ++cell) {
    const int L = cell & 1, t = cell >> 1;
    int xb, rb, hob;
    cell_bufs(cell, xb, rb, hob);
    float* C = g_c[L];
    const float* bsm = (const float*)(smem + SM_BIAS) + L * BNp;
    float facc[152];
    for (int i = 0; i < 152; ++i) facc[i] = 0.f;
    for (int it = 0; it < NIT; ++it) {
      int phr = (it < NKT), ktt = phr ? it : (it - NKT);
      int ab = phr ? rb : xb;
      int mi = 2 * L + (phr ? 1 : 0);
      const char* ah = (const char*)g_actHi[ab];
      const char* al = (const char*)g_actLo[ab];
      const char* bh = (const char*)g_WHi[mi];
      const char* bl = (const char*)g_WLo[mi];
      size_t at = (size_t)(mt * NKT + ktt) * A_TILE;
      size_t bt = (size_t)(nt * NKT + ktt) * B_TILE;
      for (int k = 0; k < BK; ++k) {
        uint32_t ao = SW128(f_row * 128 + k * 2);
        float a = __bfloat162float(*(const __nv_bfloat16*)(ah + at + ao)) +
                  __bfloat162float(*(const __nv_bfloat16*)(al + at + ao));
        for (int c2 = 0; c2 < 152; ++c2) {
          int bn = f_ch * 152 + c2;
          uint32_t bo = SW128(bn * 128 + k * 2);
          float b = __bfloat162float(*(const __nv_bfloat16*)(bh + bt + bo)) +
                    __bfloat162float(*(const __nv_bfloat16*)(bl + bt + bo));
          facc[c2] = fmaf(a, b, facc[c2]);
        }
      }
    }
    {
      char* hoHiB = (char*)g_actHi[hob];
      char* hoLoB = (char*)g_actLo[hob];
      const int m = m0 + f_row;
      for (int jh = 0; jh < 38; ++jh) {
        int col = f_ch * 152 + jh * 4;
        if (col >= 300) break;
        int hg = nt * NHs + (col >> 2);
        float i_ = sigmoid_f(facc[jh * 4 + 0] + bsm[col + 0]);
        float f_ = sigmoid_f(facc[jh * 4 + 1] + bsm[col + 1]);
        float g_ = tanh_f(facc[jh * 4 + 2] + bsm[col + 2]);
        float o_ = sigmoid_f(facc[jh * 4 + 3] + bsm[col + 3]);
        size_t ci = (size_t)hg * Bx + m;
        float c = f_ * C[ci] + i_ * g_;
        float h = o_ * tanh_f(c);
        C[ci] = c;
        int kt2 = hg >> 6, cc = hg & 63;
        size_t off = (size_t)(mt * NKT + kt2) * A_TILE + SW128(f_row * 128 + cc * 2);
        __nv_bfloat16 hi = __float2bfloat16(h);
        *(__nv_bfloat16*)(hoHiB + off) = hi;
        *(__nv_bfloat16*)(hoLoB + off) =
            __float2bfloat16(h - __bfloat162float(hi));
        if (L) Y[(size_t)m * (Tn * Hd) + (size_t)t * Hd + hg] = h;
      }
    }
    if (cell < CELLS - 1) grid_barrier(cell + 1, tid);
  }
#endif
}

// ---- host side ----------------------------------------------------------
extern "C" void kernel_launch(void* const* d_in, const int* in_sizes, int n_in,
                              void* d_out, int out_size) {
  const float* z    = (const float*)d_in[0];
  const float* Wih0 = (const float*)d_in[1];
  const float* Whh0 = (const float*)d_in[2];
  const float* bih0 = (const float*)d_in[3];
  const float* bhh0 = (const float*)d_in[4];
  const float* Wih1 = (const float*)d_in[5];
  const float* Whh1 = (const float*)d_in[6];
  const float* bih1 = (const float*)d_in[7];
  const float* bhh1 = (const float*)d_in[8];
  float* out = (float*)d_out;

  cudaFuncSetAttribute(lstm_persist_kernel,
                       cudaFuncAttributeMaxDynamicSharedMemorySize, SM_TOTAL);

  prep_kernel<<<1024, 256>>>(z, Wih0, Whh0, bih0, bhh0, Wih1, Whh1, bih1, bhh1);

  dim3 grid(NMT, NNT);  // 32 x 4 = 128 co-resident CTAs
  lstm_persist_kernel<<<grid, 256, SM_TOTAL>>>(out);
}